// round 1
// baseline (speedup 1.0000x reference)
#include <cuda_runtime.h>

// Problem constants
#define B_  8
#define C_  64
#define L_  65536
#define S_  4
#define M_  32
#define O_  64
#define G_  16384            // L_/S_
#define ROWS_ (B_*C_*S_)     // 2048
#define VROWS_ (S_*M_*C_)    // 8192

typedef unsigned long long ull;

// ---------------- device scratch (no allocs allowed) ----------------
__device__ unsigned int g_minmax[2*S_];   // [2s]=min(enc), [2s+1]=max(enc)
__device__ float        g_v[VROWS_];      // v[s][i][c] = mean_o W[s,i,c,:]

// ---------------- packed f32x2 helpers (Blackwell FFMA2 path) ----------------
__device__ __forceinline__ ull pack2(float lo, float hi) {
    ull r; asm("mov.b64 %0, {%1, %2};" : "=l"(r) : "f"(lo), "f"(hi)); return r;
}
__device__ __forceinline__ void unpack2(ull v, float& lo, float& hi) {
    asm("mov.b64 {%0, %1}, %2;" : "=f"(lo), "=f"(hi) : "l"(v));
}
__device__ __forceinline__ ull fma2(ull a, ull b, ull c) {
    ull d; asm("fma.rn.f32x2 %0, %1, %2, %3;" : "=l"(d) : "l"(a), "l"(b), "l"(c)); return d;
}
__device__ __forceinline__ ull add2(ull a, ull b) {
    ull d; asm("add.rn.f32x2 %0, %1, %2;" : "=l"(d) : "l"(a), "l"(b)); return d;
}

// ordered-uint encoding for float atomic min/max
__device__ __forceinline__ unsigned int encf(float f) {
    unsigned int u = __float_as_uint(f);
    return (u & 0x80000000u) ? ~u : (u | 0x80000000u);
}
__device__ __forceinline__ float decf(unsigned int u) {
    unsigned int v = (u & 0x80000000u) ? (u & 0x7fffffffu) : ~u;
    return __uint_as_float(v);
}

// ---------------- kernel 1: weight reduction + minmax init ----------------
// grid = VROWS_/256 = 32 blocks, 256 threads. Each thread: one (s,i,c) row,
// sum 64 contiguous O values.
__global__ void __launch_bounds__(256) prep_kernel(const float* __restrict__ W) {
    int row = blockIdx.x * 256 + threadIdx.x;      // [0, 8192)
    const float4* p = reinterpret_cast<const float4*>(W) + (size_t)row * (O_/4);
    float s = 0.f;
#pragma unroll
    for (int q = 0; q < O_/4; ++q) {
        float4 f = __ldg(&p[q]);
        s += (f.x + f.y) + (f.z + f.w);
    }
    g_v[row] = s * (1.0f / O_);
    if (blockIdx.x == 0 && threadIdx.x < 2*S_) {
        g_minmax[threadIdx.x] = (threadIdx.x & 1) ? 0u : 0xFFFFFFFFu;
    }
}

// ---------------- kernel 2: per-segment global min/max ----------------
// grid = ROWS_ (2048), one block per (b,c,s) row of G_ elements.
__global__ void __launch_bounds__(256) minmax_kernel(const float4* __restrict__ x4) {
    int row = blockIdx.x;
    int t = threadIdx.x;
    const float4* p = x4 + (size_t)row * (G_/4);
    float mn =  __int_as_float(0x7f800000);   // +inf
    float mx = -__int_as_float(0x7f800000);
#pragma unroll 4
    for (int i = 0; i < 16; ++i) {
        float4 f = __ldg(&p[i*256 + t]);
        mn = fminf(mn, fminf(fminf(f.x, f.y), fminf(f.z, f.w)));
        mx = fmaxf(mx, fmaxf(fmaxf(f.x, f.y), fmaxf(f.z, f.w)));
    }
#pragma unroll
    for (int off = 16; off > 0; off >>= 1) {
        mn = fminf(mn, __shfl_xor_sync(0xffffffffu, mn, off));
        mx = fmaxf(mx, __shfl_xor_sync(0xffffffffu, mx, off));
    }
    __shared__ float smn[8], smx[8];
    int lane = t & 31, warp = t >> 5;
    if (lane == 0) { smn[warp] = mn; smx[warp] = mx; }
    __syncthreads();
    if (t == 0) {
        float bmn = smn[0], bmx = smx[0];
#pragma unroll
        for (int w = 1; w < 8; ++w) { bmn = fminf(bmn, smn[w]); bmx = fmaxf(bmx, smx[w]); }
        int s = row & (S_ - 1);
        atomicMin(&g_minmax[2*s],     encf(bmn));
        atomicMax(&g_minmax[2*s + 1], encf(bmx));
    }
}

// ---------------- Chebyshev inner step (2 elements packed) ----------------
// acc[m] accumulates sigma_m * sum T_{m+1}(xn), sigma_m = +1 if m%4 in {0,1}.
// 4-step sign-alternating unroll: only fma2/add2, no negations.
__device__ __forceinline__ void cheb_pair(ull raw, ull SC, ull BI, ull NSC, ull NBI,
                                          ull NEG1, ull (&acc)[32]) {
    ull xn  = fma2(raw, SC, BI);      // xn  = scale*x + bias     (2 lanes)
    ull x2  = add2(xn, xn);           // 2*xn
    ull nx2 = fma2(raw, NSC, NBI);    // -2*xn
    acc[0] = add2(acc[0], xn);        // T_1 (pos)
    ull P = xn, Q = NEG1;             // P = T_1 (pos), Q = -T_0
#pragma unroll
    for (int j = 0; j < 7; ++j) {
        ull ta = fma2(x2,  P,  Q);  acc[4*j+1] = add2(acc[4*j+1], ta);  //  T_{4j+2}
        ull tb = fma2(nx2, ta, P);  acc[4*j+2] = add2(acc[4*j+2], tb);  // -T_{4j+3}
        ull tc = fma2(x2,  tb, ta); acc[4*j+3] = add2(acc[4*j+3], tc);  // -T_{4j+4}
        ull td = fma2(nx2, tc, tb); acc[4*j+4] = add2(acc[4*j+4], td);  //  T_{4j+5}
        P = td; Q = tc;
    }
    ull ta = fma2(x2,  P,  Q);  acc[29] = add2(acc[29], ta);            //  T_30
    ull tb = fma2(nx2, ta, P);  acc[30] = add2(acc[30], tb);            // -T_31
    ull tc = fma2(x2,  tb, ta); acc[31] = add2(acc[31], tc);            // -T_32
}

// ---------------- kernel 3: main — coefficients + dot + tanh + broadcast ----------------
// grid = ROWS_ (2048), one block per (b,c,s) row.
__global__ void __launch_bounds__(256) main_kernel(const float4* __restrict__ x4,
                                                   float4* __restrict__ out4) {
    int row = blockIdx.x;
    int s = row & (S_ - 1);
    int c = (row >> 2) & (C_ - 1);
    int t = threadIdx.x;

    __shared__ float sAw[32];
    __shared__ float sAc;
    __shared__ float warpsum[8];
    __shared__ float sres;

    // A coefficients for this (s,c): sigma and 1/G folded in.
    if (t < 32) {
        const float* vb = g_v + c;     // v[s][i][c] = g_v[(s*32+i)*64 + c]
        int m = t;
        float a;
        if (m == 0)       a = vb[(s*M_ + 0)*C_] + 0.5f * vb[(s*M_ + 2)*C_];
        else if (m <= 29) a = 0.5f * (vb[(s*M_ + m)*C_] + vb[(s*M_ + m + 2)*C_]);
        else              a = 0.5f * vb[(s*M_ + m)*C_];
        float sg = ((m & 2) == 0) ? 1.0f : -1.0f;
        sAw[m] = sg * a * (1.0f / (float)G_);
        if (m == 0) sAc = 0.5f * vb[(s*M_ + 1)*C_];   // A_0 (constant, m_0 = 1)
    }
    __syncthreads();

    float mn = decf(g_minmax[2*s]);
    float mx = decf(g_minmax[2*s + 1]);
    float scale = 2.0f / (mx - mn);
    float bias  = -mn * scale - 1.0f;

    ull SC   = pack2(scale, scale);
    ull BI   = pack2(bias, bias);
    ull NSC  = pack2(-2.0f*scale, -2.0f*scale);
    ull NBI  = pack2(-2.0f*bias,  -2.0f*bias);
    ull NEG1 = pack2(-1.0f, -1.0f);

    ull acc[32];
#pragma unroll
    for (int m = 0; m < 32; ++m) acc[m] = 0ull;

    const float4* p = x4 + (size_t)row * (G_/4);
#pragma unroll 2
    for (int i = 0; i < 16; ++i) {
        float4 f = __ldg(&p[i*256 + t]);
        cheb_pair(pack2(f.x, f.y), SC, BI, NSC, NBI, NEG1, acc);
        cheb_pair(pack2(f.z, f.w), SC, BI, NSC, NBI, NEG1, acc);
    }

    // Per-thread dot with A (packed), then block-reduce a single scalar.
    ull dp = 0ull;
#pragma unroll
    for (int m = 0; m < 32; ++m) {
        float a = sAw[m];
        dp = fma2(pack2(a, a), acc[m], dp);
    }
    float lo, hi; unpack2(dp, lo, hi);
    float d = lo + hi;
#pragma unroll
    for (int off = 16; off > 0; off >>= 1)
        d += __shfl_xor_sync(0xffffffffu, d, off);
    int lane = t & 31, warp = t >> 5;
    if (lane == 0) warpsum[warp] = d;
    __syncthreads();
    if (t == 0) {
        float tot = sAc;
#pragma unroll
        for (int w = 0; w < 8; ++w) tot += warpsum[w];
        sres = tanhf(tot);
    }
    __syncthreads();

    float r = sres;
    float4 rv = make_float4(r, r, r, r);
    float4* q = out4 + (size_t)row * (G_/4);
#pragma unroll 4
    for (int i = 0; i < 16; ++i) q[i*256 + t] = rv;
}

// ---------------- launch ----------------
extern "C" void kernel_launch(void* const* d_in, const int* in_sizes, int n_in,
                              void* d_out, int out_size) {
    const float* x = (const float*)d_in[0];
    const float* w = (const float*)d_in[1];
    // defensive: identify by element count (x = 33554432, W = 524288)
    if (n_in >= 2 && in_sizes[0] < in_sizes[1]) {
        const float* tmp = x; x = w; w = tmp;
    }
    prep_kernel<<<VROWS_/256, 256>>>(w);
    minmax_kernel<<<ROWS_, 256>>>((const float4*)x);
    main_kernel<<<ROWS_, 256>>>((const float4*)x, (float4*)d_out);
}

// round 2
// speedup vs baseline: 1.0850x; 1.0850x over previous
#include <cuda_runtime.h>

// Problem constants
#define B_  8
#define C_  64
#define L_  65536
#define S_  4
#define M_  32
#define O_  64
#define G_  16384            // L_/S_
#define ROWS_ (B_*C_*S_)     // 2048
#define VROWS_ (S_*M_*C_)    // 8192

typedef unsigned long long ull;

// ---------------- device scratch (no allocs allowed) ----------------
__device__ float  g_v[VROWS_];        // v[s][i][c] = mean_o W[s,i,c,:]
__device__ float2 g_rowmm[ROWS_];     // per-row {min, max}, rewritten each replay

// ---------------- packed f32x2 helpers ----------------
__device__ __forceinline__ ull pack2(float lo, float hi) {
    ull r; asm("mov.b64 %0, {%1, %2};" : "=l"(r) : "f"(lo), "f"(hi)); return r;
}
__device__ __forceinline__ void unpack2(ull v, float& lo, float& hi) {
    asm("mov.b64 {%0, %1}, %2;" : "=f"(lo), "=f"(hi) : "l"(v));
}
__device__ __forceinline__ ull fma2(ull a, ull b, ull c) {
    ull d; asm("fma.rn.f32x2 %0, %1, %2, %3;" : "=l"(d) : "l"(a), "l"(b), "l"(c)); return d;
}
__device__ __forceinline__ ull add2(ull a, ull b) {
    ull d; asm("add.rn.f32x2 %0, %1, %2;" : "=l"(d) : "l"(a), "l"(b)); return d;
}
__device__ __forceinline__ ull sub2(ull a, ull b) {
    ull d; asm("sub.rn.f32x2 %0, %1, %2;" : "=l"(d) : "l"(a), "l"(b)); return d;
}

// ---------------- kernel A: per-row min/max + weight reduction ----------------
// grid = ROWS_ + 32. Blocks [0,2048): minmax of one (b,c,s) row -> g_rowmm.
// Blocks [2048,2080): weight reduction (8192 rows of 64 floats) -> g_v.
__global__ void __launch_bounds__(256) pass_a_kernel(const float4* __restrict__ x4,
                                                     const float* __restrict__ W) {
    int blk = blockIdx.x;
    int t = threadIdx.x;
    if (blk >= ROWS_) {
        int row = (blk - ROWS_) * 256 + t;          // [0, 8192)
        const float4* p = reinterpret_cast<const float4*>(W) + (size_t)row * (O_/4);
        float s = 0.f;
#pragma unroll
        for (int q = 0; q < O_/4; ++q) {
            float4 f = __ldg(&p[q]);
            s += (f.x + f.y) + (f.z + f.w);
        }
        g_v[row] = s * (1.0f / O_);
        return;
    }
    int row = blk;
    const float4* p = x4 + (size_t)row * (G_/4);
    float mn =  __int_as_float(0x7f800000);
    float mx = -__int_as_float(0x7f800000);
#pragma unroll 4
    for (int i = 0; i < 16; ++i) {
        float4 f = __ldg(&p[i*256 + t]);
        mn = fminf(mn, fminf(fminf(f.x, f.y), fminf(f.z, f.w)));
        mx = fmaxf(mx, fmaxf(fmaxf(f.x, f.y), fmaxf(f.z, f.w)));
    }
#pragma unroll
    for (int off = 16; off > 0; off >>= 1) {
        mn = fminf(mn, __shfl_xor_sync(0xffffffffu, mn, off));
        mx = fmaxf(mx, __shfl_xor_sync(0xffffffffu, mx, off));
    }
    __shared__ float smn[8], smx[8];
    int lane = t & 31, warp = t >> 5;
    if (lane == 0) { smn[warp] = mn; smx[warp] = mx; }
    __syncthreads();
    if (t == 0) {
        float bmn = smn[0], bmx = smx[0];
#pragma unroll
        for (int w = 1; w < 8; ++w) { bmn = fminf(bmn, smn[w]); bmx = fmaxf(bmx, smx[w]); }
        g_rowmm[row] = make_float2(bmn, bmx);
    }
}

// ---------------- Clenshaw step: P(xn) for 2 packed elements ----------------
// APK[j] = packed Aw_{j+1}, j = 0..31 (Aw includes 1/G).
// f(xn) = sum_{k=1}^{32} Aw_k T_k(xn);  acc1 += xn*b1,  acc2 += b2,  f-sum = acc1 - acc2.
__device__ __forceinline__ void clenshaw_pair(ull raw, ull SC, ull BI,
                                              const ull (&APK)[32],
                                              ull& acc1, ull& acc2) {
    ull xn = fma2(raw, SC, BI);       // xn = scale*x + bias
    ull x2 = add2(xn, xn);            // 2*xn
    ull b1 = APK[31];                 // b_32
    ull bn = fma2(x2, b1, APK[30]);   // b_31 (b_33 = 0)
    ull b2 = b1; b1 = bn;
#pragma unroll
    for (int j = 29; j >= 0; --j) {   // b_30 .. b_1
        ull tt = sub2(APK[j], b2);
        bn = fma2(x2, b1, tt);
        b2 = b1; b1 = bn;
    }
    acc1 = fma2(xn, b1, acc1);
    acc2 = add2(acc2, b2);
}

// ---------------- kernel B: main ----------------
// grid = ROWS_, one block per (b,c,s) row.
__global__ void __launch_bounds__(256, 2) main_kernel(const float4* __restrict__ x4,
                                                      float4* __restrict__ out4) {
    int row = blockIdx.x;
    int s = row & (S_ - 1);
    int c = (row >> 2) & (C_ - 1);
    int t = threadIdx.x;

    __shared__ float sA[33];          // sA[k] = Aw_k, k = 1..32
    __shared__ float sAc;             // constant term A_0
    __shared__ float2 smm[8];
    __shared__ float sSB[2];          // {scale, bias}
    __shared__ float warpsum[8];
    __shared__ float sres;

    // --- A coefficients for this (s,c), 1/G folded in ---
    if (t < 32) {
        const float* vb = g_v + c;    // v[s][i][c] = g_v[(s*32+i)*64 + c]
        int k = t + 1;                // mode 1..32
        float a;
        if (k == 1)       a = vb[(s*M_ + 0)*C_] + 0.5f * vb[(s*M_ + 2)*C_];
        else if (k <= 30) a = 0.5f * (vb[(s*M_ + k - 1)*C_] + vb[(s*M_ + k + 1)*C_]);
        else              a = 0.5f * vb[(s*M_ + k - 1)*C_];
        sA[k] = a * (1.0f / (float)G_);
        if (k == 1) sAc = 0.5f * vb[(s*M_ + 1)*C_];
    }

    // --- segment min/max from per-row table (512 rows, stride S_) ---
    {
        float2 a = g_rowmm[s + S_ * t];
        float2 b = g_rowmm[s + S_ * (t + 256)];
        float mn = fminf(a.x, b.x);
        float mx = fmaxf(a.y, b.y);
#pragma unroll
        for (int off = 16; off > 0; off >>= 1) {
            mn = fminf(mn, __shfl_xor_sync(0xffffffffu, mn, off));
            mx = fmaxf(mx, __shfl_xor_sync(0xffffffffu, mx, off));
        }
        int lane = t & 31, warp = t >> 5;
        if (lane == 0) smm[warp] = make_float2(mn, mx);
        __syncthreads();
        if (t == 0) {
            float bmn = smm[0].x, bmx = smm[0].y;
#pragma unroll
            for (int w = 1; w < 8; ++w) { bmn = fminf(bmn, smm[w].x); bmx = fmaxf(bmx, smm[w].y); }
            float scale = 2.0f / (bmx - bmn);
            sSB[0] = scale;
            sSB[1] = -bmn * scale - 1.0f;
        }
        __syncthreads();
    }

    float scale = sSB[0], bias = sSB[1];
    ull SC = pack2(scale, scale);
    ull BI = pack2(bias, bias);

    ull APK[32];
#pragma unroll
    for (int j = 0; j < 32; ++j) {
        float a = sA[j + 1];
        APK[j] = pack2(a, a);
    }

    ull acc1 = 0ull, acc2 = 0ull;
    const float4* p = x4 + (size_t)row * (G_/4) + t;

    float4 f = __ldcs(&p[0]);
    for (int i = 0; i < 16; ++i) {
        float4 fn = (i < 15) ? __ldcs(&p[(i+1)*256]) : f;   // prefetch next
        clenshaw_pair(pack2(f.x, f.y), SC, BI, APK, acc1, acc2);
        clenshaw_pair(pack2(f.z, f.w), SC, BI, APK, acc1, acc2);
        f = fn;
    }

    // --- reduce: sum over elements of (xn*b1 - b2) ---
    float lo1, hi1, lo2, hi2;
    unpack2(acc1, lo1, hi1);
    unpack2(acc2, lo2, hi2);
    float d = (lo1 + hi1) - (lo2 + hi2);
#pragma unroll
    for (int off = 16; off > 0; off >>= 1)
        d += __shfl_xor_sync(0xffffffffu, d, off);
    int lane = t & 31, warp = t >> 5;
    if (lane == 0) warpsum[warp] = d;
    __syncthreads();
    if (t == 0) {
        float tot = sAc;
#pragma unroll
        for (int w = 0; w < 8; ++w) tot += warpsum[w];
        sres = tanhf(tot);
    }
    __syncthreads();

    float r = sres;
    float4 rv = make_float4(r, r, r, r);
    float4* q = out4 + (size_t)row * (G_/4) + t;
#pragma unroll 4
    for (int i = 0; i < 16; ++i) __stcs(&q[i*256], rv);
}

// ---------------- launch ----------------
extern "C" void kernel_launch(void* const* d_in, const int* in_sizes, int n_in,
                              void* d_out, int out_size) {
    const float* x = (const float*)d_in[0];
    const float* w = (const float*)d_in[1];
    if (n_in >= 2 && in_sizes[0] < in_sizes[1]) {
        const float* tmp = x; x = w; w = tmp;
    }
    pass_a_kernel<<<ROWS_ + VROWS_/256, 256>>>((const float4*)x, w);
    main_kernel<<<ROWS_, 256>>>((const float4*)x, (float4*)d_out);
}